// round 4
// baseline (speedup 1.0000x reference)
#include <cuda_runtime.h>

#define NBATCH 2
#define LSEQ   2048
#define EMB    1024
#define NHEAD  16
#define HD     64
#define ODIM   1024

// Scratch (static device arrays — no allocations allowed)
__device__ float g_Qp[NBATCH * LSEQ * EMB];
__device__ float g_Kp[NBATCH * LSEQ * EMB];
__device__ float g_Vp[NBATCH * LSEQ * EMB];
__device__ float g_AO[NBATCH * LSEQ * EMB];

// ---------------------------------------------------------------------------
// Per-head projection: Y[r][e] = sum_d X[r][d] * W[e][d]
// X flat (N*L*H, 64) rows (head slice is contiguous), W is (64, 64) row-major.
// One block = 64 rows. 256 threads as 16x16, 4x4 micro-tile each.
// ---------------------------------------------------------------------------
__global__ __launch_bounds__(256) void proj_kernel(
    const float* __restrict__ X, const float* __restrict__ W,
    float* __restrict__ Y)
{
    __shared__ float Xs[64][65];
    __shared__ float Ws[64][65];
    const int t  = threadIdx.x;
    const int tx = t & 15, ty = t >> 4;
    const int rb = blockIdx.x << 6;

#pragma unroll
    for (int rep = 0; rep < 4; ++rep) {
        int idx = rep * 256 + t;
        int r   = idx >> 4;
        int d0  = (idx & 15) << 2;
        float4 xv = *(const float4*)(X + (size_t)(rb + r) * 64 + d0);
        Xs[r][d0 + 0] = xv.x; Xs[r][d0 + 1] = xv.y;
        Xs[r][d0 + 2] = xv.z; Xs[r][d0 + 3] = xv.w;
        float4 wv = *(const float4*)(W + r * 64 + d0);
        Ws[r][d0 + 0] = wv.x; Ws[r][d0 + 1] = wv.y;
        Ws[r][d0 + 2] = wv.z; Ws[r][d0 + 3] = wv.w;
    }
    __syncthreads();

    float acc[4][4] = {};
#pragma unroll 8
    for (int d = 0; d < 64; ++d) {
        float a0 = Xs[ty * 4 + 0][d], a1 = Xs[ty * 4 + 1][d];
        float a2 = Xs[ty * 4 + 2][d], a3 = Xs[ty * 4 + 3][d];
        float b0 = Ws[tx * 4 + 0][d], b1 = Ws[tx * 4 + 1][d];
        float b2 = Ws[tx * 4 + 2][d], b3 = Ws[tx * 4 + 3][d];
        acc[0][0] += a0 * b0; acc[0][1] += a0 * b1; acc[0][2] += a0 * b2; acc[0][3] += a0 * b3;
        acc[1][0] += a1 * b0; acc[1][1] += a1 * b1; acc[1][2] += a1 * b2; acc[1][3] += a1 * b3;
        acc[2][0] += a2 * b0; acc[2][1] += a2 * b1; acc[2][2] += a2 * b2; acc[2][3] += a2 * b3;
        acc[3][0] += a3 * b0; acc[3][1] += a3 * b1; acc[3][2] += a3 * b2; acc[3][3] += a3 * b3;
    }

#pragma unroll
    for (int a = 0; a < 4; ++a) {
        float4 o = make_float4(acc[a][0], acc[a][1], acc[a][2], acc[a][3]);
        *(float4*)(Y + (size_t)(rb + ty * 4 + a) * 64 + tx * 4) = o;
    }
}

// ---------------------------------------------------------------------------
// Flash attention, fp32. One block per (q-tile of 64, n*H+h).
// 256 threads as 16x16; thread (tx,ty) owns S/O rows ty*4..+3, cols tx*4..+3.
// Online softmax: row stats live in registers, replicated across the 16
// tx-lanes of each half-warp via shfl-xor (no smem stats, no extra barriers).
// Dynamic smem: Qt[64][64] (Q transposed), Ks[64][65], Vs[64][64], Ps[64][65].
// ---------------------------------------------------------------------------
#define FLASH_SMEM_FLOATS (4096 + 4160 + 4096 + 4160)
#define FLASH_SMEM_BYTES  (FLASH_SMEM_FLOATS * 4)

__global__ __launch_bounds__(256) void flash_kernel(
    const float* __restrict__ Qp, const float* __restrict__ Kp,
    const float* __restrict__ Vp, float* __restrict__ AO)
{
    extern __shared__ float sm[];
    float (*Qt)[64] = (float(*)[64])(sm);                        // [d][i]
    float (*Ks)[65] = (float(*)[65])(sm + 4096);                 // [j][d]
    float (*Vs)[64] = (float(*)[64])(sm + 4096 + 4160);          // [j][d]
    float (*Ps)[65] = (float(*)[65])(sm + 4096 + 4160 + 4096);   // [i][j]

    const int t  = threadIdx.x;
    const int tx = t & 15, ty = t >> 4;
    const int nh = blockIdx.y;
    const int n  = nh >> 4, h = nh & 15;
    const int qb = blockIdx.x << 6;
    const size_t base = ((size_t)n * LSEQ) * EMB + (size_t)h * HD;

    // Load Q tile, transposed into Qt[d][i]
#pragma unroll
    for (int rep = 0; rep < 4; ++rep) {
        int idx = rep * 256 + t;
        int r   = idx >> 4;
        int d0  = (idx & 15) << 2;
        float4 qv = *(const float4*)(Qp + base + (size_t)(qb + r) * EMB + d0);
        Qt[d0 + 0][r] = qv.x; Qt[d0 + 1][r] = qv.y;
        Qt[d0 + 2][r] = qv.z; Qt[d0 + 3][r] = qv.w;
    }

    float m_run[4], l_run[4], O[4][4];
#pragma unroll
    for (int a = 0; a < 4; ++a) {
        m_run[a] = -1e30f; l_run[a] = 0.f;
        O[a][0] = O[a][1] = O[a][2] = O[a][3] = 0.f;
    }
    const float scale = 0.03125f;  // 1/sqrt(EMBED) = 1/32

    for (int kb = 0; kb < LSEQ; kb += 64) {
        __syncthreads();  // protects Ks/Vs/Ps reuse; first iter orders Qt stores
        // Load K and V tiles (natural layout, Ks padded)
#pragma unroll
        for (int rep = 0; rep < 4; ++rep) {
            int idx = rep * 256 + t;
            int j   = idx >> 4;
            int d0  = (idx & 15) << 2;
            float4 kv = *(const float4*)(Kp + base + (size_t)(kb + j) * EMB + d0);
            Ks[j][d0 + 0] = kv.x; Ks[j][d0 + 1] = kv.y;
            Ks[j][d0 + 2] = kv.z; Ks[j][d0 + 3] = kv.w;
            float4 vv = *(const float4*)(Vp + base + (size_t)(kb + j) * EMB + d0);
            *(float4*)&Vs[j][d0] = vv;
        }
        __syncthreads();

        // S = Q @ K^T (4x4 micro-tile)
        float s[4][4] = {};
#pragma unroll 8
        for (int d = 0; d < 64; ++d) {
            float4 q4 = *(const float4*)&Qt[d][ty * 4];  // rows a=0..3
            float b0 = Ks[tx * 4 + 0][d], b1 = Ks[tx * 4 + 1][d];
            float b2 = Ks[tx * 4 + 2][d], b3 = Ks[tx * 4 + 3][d];
            s[0][0] += q4.x * b0; s[0][1] += q4.x * b1; s[0][2] += q4.x * b2; s[0][3] += q4.x * b3;
            s[1][0] += q4.y * b0; s[1][1] += q4.y * b1; s[1][2] += q4.y * b2; s[1][3] += q4.y * b3;
            s[2][0] += q4.z * b0; s[2][1] += q4.z * b1; s[2][2] += q4.z * b2; s[2][3] += q4.z * b3;
            s[3][0] += q4.w * b0; s[3][1] += q4.w * b1; s[3][2] += q4.w * b2; s[3][3] += q4.w * b3;
        }

        // Online softmax (row stats replicated across tx-lanes via shfl)
        float mt[4];
#pragma unroll
        for (int a = 0; a < 4; ++a) {
            s[a][0] *= scale; s[a][1] *= scale; s[a][2] *= scale; s[a][3] *= scale;
            mt[a] = fmaxf(fmaxf(s[a][0], s[a][1]), fmaxf(s[a][2], s[a][3]));
        }
#pragma unroll
        for (int off = 8; off >= 1; off >>= 1) {
#pragma unroll
            for (int a = 0; a < 4; ++a)
                mt[a] = fmaxf(mt[a], __shfl_xor_sync(0xffffffffu, mt[a], off));
        }
        float p[4][4], rs[4];
#pragma unroll
        for (int a = 0; a < 4; ++a) {
            float mn = fmaxf(m_run[a], mt[a]);
            float c  = __expf(m_run[a] - mn);
            m_run[a] = mn;
            p[a][0] = __expf(s[a][0] - mn); p[a][1] = __expf(s[a][1] - mn);
            p[a][2] = __expf(s[a][2] - mn); p[a][3] = __expf(s[a][3] - mn);
            rs[a] = (p[a][0] + p[a][1]) + (p[a][2] + p[a][3]);
            l_run[a] *= c;
            O[a][0] *= c; O[a][1] *= c; O[a][2] *= c; O[a][3] *= c;
        }
#pragma unroll
        for (int off = 8; off >= 1; off >>= 1) {
#pragma unroll
            for (int a = 0; a < 4; ++a)
                rs[a] += __shfl_xor_sync(0xffffffffu, rs[a], off);
        }
#pragma unroll
        for (int a = 0; a < 4; ++a) l_run[a] += rs[a];

        // P -> smem for the PV GEMM
#pragma unroll
        for (int a = 0; a < 4; ++a) {
            Ps[ty * 4 + a][tx * 4 + 0] = p[a][0];
            Ps[ty * 4 + a][tx * 4 + 1] = p[a][1];
            Ps[ty * 4 + a][tx * 4 + 2] = p[a][2];
            Ps[ty * 4 + a][tx * 4 + 3] = p[a][3];
        }
        __syncthreads();

        // O += P @ V (thread owns O rows ty*4..+3, cols d = tx*4..+3)
#pragma unroll 4
        for (int j = 0; j < 64; ++j) {
            float p0 = Ps[ty * 4 + 0][j], p1 = Ps[ty * 4 + 1][j];
            float p2 = Ps[ty * 4 + 2][j], p3 = Ps[ty * 4 + 3][j];
            float4 v4 = *(const float4*)&Vs[j][tx * 4];
            O[0][0] += p0 * v4.x; O[0][1] += p0 * v4.y; O[0][2] += p0 * v4.z; O[0][3] += p0 * v4.w;
            O[1][0] += p1 * v4.x; O[1][1] += p1 * v4.y; O[1][2] += p1 * v4.z; O[1][3] += p1 * v4.w;
            O[2][0] += p2 * v4.x; O[2][1] += p2 * v4.y; O[2][2] += p2 * v4.z; O[2][3] += p2 * v4.w;
            O[3][0] += p3 * v4.x; O[3][1] += p3 * v4.y; O[3][2] += p3 * v4.z; O[3][3] += p3 * v4.w;
        }
    }

    // Epilogue: normalize and store
#pragma unroll
    for (int a = 0; a < 4; ++a) {
        float inv = 1.0f / l_run[a];
        float4 o = make_float4(O[a][0] * inv, O[a][1] * inv,
                               O[a][2] * inv, O[a][3] * inv);
        *(float4*)(AO + base + (size_t)(qb + ty * 4 + a) * EMB + tx * 4) = o;
    }
}

// ---------------------------------------------------------------------------
// Output projection: Y[r][o] = sum_i A[r][i] * Wout[o][i] + bout[o]
// A is (4096, 1024), Wout (1024, 1024). 64x64 tiles, k-chunks of 64.
// ---------------------------------------------------------------------------
__global__ __launch_bounds__(256) void outproj_kernel(
    const float* __restrict__ A, const float* __restrict__ W,
    const float* __restrict__ bias, float* __restrict__ Y)
{
    __shared__ float As[64][65];
    __shared__ float Bs[64][65];
    const int t  = threadIdx.x;
    const int tx = t & 15, ty = t >> 4;
    const int ob = blockIdx.x << 6;
    const int rb = blockIdx.y << 6;

    float acc[4][4] = {};
    for (int kc = 0; kc < EMB; kc += 64) {
        __syncthreads();
#pragma unroll
        for (int rep = 0; rep < 4; ++rep) {
            int idx = rep * 256 + t;
            int r   = idx >> 4;
            int d0  = (idx & 15) << 2;
            float4 av = *(const float4*)(A + (size_t)(rb + r) * EMB + kc + d0);
            As[r][d0 + 0] = av.x; As[r][d0 + 1] = av.y;
            As[r][d0 + 2] = av.z; As[r][d0 + 3] = av.w;
            float4 wv = *(const float4*)(W + (size_t)(ob + r) * EMB + kc + d0);
            Bs[r][d0 + 0] = wv.x; Bs[r][d0 + 1] = wv.y;
            Bs[r][d0 + 2] = wv.z; Bs[r][d0 + 3] = wv.w;
        }
        __syncthreads();
#pragma unroll 8
        for (int d = 0; d < 64; ++d) {
            float a0 = As[ty * 4 + 0][d], a1 = As[ty * 4 + 1][d];
            float a2 = As[ty * 4 + 2][d], a3 = As[ty * 4 + 3][d];
            float b0 = Bs[tx * 4 + 0][d], b1 = Bs[tx * 4 + 1][d];
            float b2 = Bs[tx * 4 + 2][d], b3 = Bs[tx * 4 + 3][d];
            acc[0][0] += a0 * b0; acc[0][1] += a0 * b1; acc[0][2] += a0 * b2; acc[0][3] += a0 * b3;
            acc[1][0] += a1 * b0; acc[1][1] += a1 * b1; acc[1][2] += a1 * b2; acc[1][3] += a1 * b3;
            acc[2][0] += a2 * b0; acc[2][1] += a2 * b1; acc[2][2] += a2 * b2; acc[2][3] += a2 * b3;
            acc[3][0] += a3 * b0; acc[3][1] += a3 * b1; acc[3][2] += a3 * b2; acc[3][3] += a3 * b3;
        }
    }

#pragma unroll
    for (int a = 0; a < 4; ++a) {
        float4 o;
        o.x = acc[a][0] + bias[ob + tx * 4 + 0];
        o.y = acc[a][1] + bias[ob + tx * 4 + 1];
        o.z = acc[a][2] + bias[ob + tx * 4 + 2];
        o.w = acc[a][3] + bias[ob + tx * 4 + 3];
        *(float4*)(Y + (size_t)(rb + ty * 4 + a) * EMB + ob + tx * 4) = o;
    }
}

// ---------------------------------------------------------------------------
extern "C" void kernel_launch(void* const* d_in, const int* in_sizes, int n_in,
                              void* d_out, int out_size)
{
    (void)in_sizes; (void)n_in; (void)out_size;
    const float* values = (const float*)d_in[0];
    const float* keys   = (const float*)d_in[1];
    const float* query  = (const float*)d_in[2];
    const float* Wv     = (const float*)d_in[3];
    const float* Wk     = (const float*)d_in[4];
    const float* Wq     = (const float*)d_in[5];
    const float* Wout   = (const float*)d_in[6];
    const float* bout   = (const float*)d_in[7];
    float* out = (float*)d_out;

    float *Qp, *Kp, *Vp, *AO;
    cudaGetSymbolAddress((void**)&Qp, g_Qp);
    cudaGetSymbolAddress((void**)&Kp, g_Kp);
    cudaGetSymbolAddress((void**)&Vp, g_Vp);
    cudaGetSymbolAddress((void**)&AO, g_AO);

    cudaFuncSetAttribute(flash_kernel,
                         cudaFuncAttributeMaxDynamicSharedMemorySize,
                         FLASH_SMEM_BYTES);

    const int projBlocks = (NBATCH * LSEQ * NHEAD) / 64;  // 1024
    proj_kernel<<<projBlocks, 256>>>(values, Wv, Vp);
    proj_kernel<<<projBlocks, 256>>>(keys,   Wk, Kp);
    proj_kernel<<<projBlocks, 256>>>(query,  Wq, Qp);

    flash_kernel<<<dim3(LSEQ / 64, NBATCH * NHEAD), 256, FLASH_SMEM_BYTES>>>(
        Qp, Kp, Vp, AO);

    outproj_kernel<<<dim3(ODIM / 64, (NBATCH * LSEQ) / 64), 256>>>(
        AO, Wout, bout, out);
}